// round 1
// baseline (speedup 1.0000x reference)
#include <cuda_runtime.h>
#include <math.h>

// Problem constants (fixed by the dataset)
#define N_TOK 32768
#define D     256
#define E     8
#define H     1024

// Expert-kernel tiling
#define BM 64      // tokens per block
#define BH 64      // hidden-chunk per iteration
#define THREADS 256

// -------- scratch (static device globals; no runtime allocation) --------
__device__ int   g_cnt[E];
__device__ int   g_tok[E * N_TOK];
__device__ float g_wgt[E * N_TOK];

// ---------------- init: zero out-region + expert counters ----------------
__global__ void init_kernel(float* __restrict__ out) {
    int i = blockIdx.x * blockDim.x + threadIdx.x;
    if (i < (N_TOK * D) / 4) ((float4*)out)[i] = make_float4(0.f, 0.f, 0.f, 0.f);
    if (i < E) g_cnt[i] = 0;
}

// ---------------- router: logits -> softmax -> top-2 -> gather lists ----
__global__ void router_kernel(const float* __restrict__ x,
                              const float* __restrict__ grad,
                              const float* __restrict__ Wr,
                              const float* __restrict__ br,
                              float* __restrict__ probs_out) {
    int warp = (blockIdx.x * blockDim.x + threadIdx.x) >> 5;
    int lane = threadIdx.x & 31;
    if (warp >= N_TOK) return;
    int n = warp;

    float acc[E];
#pragma unroll
    for (int e = 0; e < E; e++) acc[e] = 0.f;

    const float* xr = x + (size_t)n * D;
    for (int d = lane; d < D; d += 32) {
        float xv = xr[d];
        const float* wrow = Wr + d * E;   // Wr is [D+1, E] row-major
#pragma unroll
        for (int e = 0; e < E; e++) acc[e] += xv * wrow[e];
    }
#pragma unroll
    for (int e = 0; e < E; e++) {
#pragma unroll
        for (int off = 16; off > 0; off >>= 1)
            acc[e] += __shfl_xor_sync(0xffffffffu, acc[e], off);
    }

    if (lane == 0) {
        float g = grad[n];
        const float* wg = Wr + D * E;     // grad row of Wr
        float p[E];
        float mx = -1e30f;
#pragma unroll
        for (int e = 0; e < E; e++) {
            p[e] = acc[e] + g * wg[e] + br[e];
            mx = fmaxf(mx, p[e]);
        }
        float s = 0.f;
#pragma unroll
        for (int e = 0; e < E; e++) { p[e] = expf(p[e] - mx); s += p[e]; }
        float inv = 1.f / s;
#pragma unroll
        for (int e = 0; e < E; e++) { p[e] *= inv; probs_out[n * E + e] = p[e]; }

        // top-2 (ties -> lowest index first, matching jax.lax.top_k)
        int i1 = 0; float v1 = p[0];
#pragma unroll
        for (int e = 1; e < E; e++) if (p[e] > v1) { v1 = p[e]; i1 = e; }
        int i2 = -1; float v2 = -1.f;
#pragma unroll
        for (int e = 0; e < E; e++) if (e != i1 && p[e] > v2) { v2 = p[e]; i2 = e; }

        int s1 = atomicAdd(&g_cnt[i1], 1);
        g_tok[i1 * N_TOK + s1] = n; g_wgt[i1 * N_TOK + s1] = v1;
        int s2 = atomicAdd(&g_cnt[i2], 1);
        g_tok[i2 * N_TOK + s2] = n; g_wgt[i2 * N_TOK + s2] = v2;
    }
}

// ---------------- fused expert MLP: y = gelu(x W1 + b1) W2 + b2 ----------
__device__ __forceinline__ float gelu_exact(float v) {
    return 0.5f * v * (1.f + erff(v * 0.70710678118654752f));
}

// Dynamic smem layout:
//   xs  [BM][D]   gathered tokens          (64 KB)
//   ws  [BH*D]    W1 chunk ([D][BH]) / W2 chunk ([BH][D]) (64 KB, reused)
//   hs  [BM][BH]  gelu activations         (16 KB)
//   stok[BM], swgt[BM]
__global__ void __launch_bounds__(THREADS, 1) expert_kernel(
    const float* __restrict__ x,
    const float* __restrict__ W1, const float* __restrict__ b1,
    const float* __restrict__ W2, const float* __restrict__ b2,
    float* __restrict__ out)
{
    int e = blockIdx.y;
    int cnt = g_cnt[e];
    int base = blockIdx.x * BM;
    if (base >= cnt) return;

    extern __shared__ float smem[];
    float* xs = smem;                       // BM*D
    float* ws = xs + BM * D;                // BH*D
    float* hs = ws + BH * D;                // BM*BH
    int*   stok = (int*)(hs + BM * BH);
    float* swgt = (float*)(stok + BM);

    int t = threadIdx.x;
    if (t < BM) {
        int idx = base + t;
        if (idx < cnt) { stok[t] = g_tok[e * N_TOK + idx]; swgt[t] = g_wgt[e * N_TOK + idx]; }
        else           { stok[t] = 0;                      swgt[t] = 0.f; }
    }
    __syncthreads();

    // gather x rows (float4, coalesced)
    for (int i = t; i < BM * (D / 4); i += THREADS) {
        int m = i / (D / 4), c = i % (D / 4);
        ((float4*)(xs + m * D))[c] = ((const float4*)(x + (size_t)stok[m] * D))[c];
    }

    const int tx = t & 63;         // GEMM2: d0 = tx*4
    const int ty = t >> 6;         // GEMM2: tokens m = ty + 4k
    const int hx = t & 15;         // GEMM1: h = hx*4
    const int my = t >> 4;         // GEMM1: tokens m = my*4 + r

    float4 yacc[16];
#pragma unroll
    for (int k = 0; k < 16; k++) yacc[k] = make_float4(0.f, 0.f, 0.f, 0.f);

    const float* W1e = W1 + (size_t)e * D * H;
    const float* W2e = W2 + (size_t)e * H * D;
    const float* b1e = b1 + e * H;

    for (int hc = 0; hc < H; hc += BH) {
        __syncthreads();  // xs ready / ws free from previous GEMM2
        // stage W1 chunk: ws[d*BH + j] = W1e[d][hc + j]
        for (int i = t; i < D * (BH / 4); i += THREADS) {
            int d = i / (BH / 4), c = i % (BH / 4);
            ((float4*)(ws + d * BH))[c] = *((const float4*)(W1e + (size_t)d * H + hc) + c);
        }
        __syncthreads();

        // GEMM1: 4 tokens x 4 h per thread, over full D
        float4 ha[4];
#pragma unroll
        for (int r = 0; r < 4; r++) ha[r] = make_float4(0.f, 0.f, 0.f, 0.f);
        for (int d = 0; d < D; d += 4) {
            float4 w0 = *(const float4*)&ws[(d + 0) * BH + hx * 4];
            float4 w1v = *(const float4*)&ws[(d + 1) * BH + hx * 4];
            float4 w2v = *(const float4*)&ws[(d + 2) * BH + hx * 4];
            float4 w3v = *(const float4*)&ws[(d + 3) * BH + hx * 4];
#pragma unroll
            for (int r = 0; r < 4; r++) {
                float4 xv = *(const float4*)&xs[(my * 4 + r) * D + d];
                ha[r].x += xv.x * w0.x + xv.y * w1v.x + xv.z * w2v.x + xv.w * w3v.x;
                ha[r].y += xv.x * w0.y + xv.y * w1v.y + xv.z * w2v.y + xv.w * w3v.y;
                ha[r].z += xv.x * w0.z + xv.y * w1v.z + xv.z * w2v.z + xv.w * w3v.z;
                ha[r].w += xv.x * w0.w + xv.y * w1v.w + xv.z * w2v.w + xv.w * w3v.w;
            }
        }
        // bias + exact gelu -> hs
        float4 bb1 = *((const float4*)(b1e + hc) + hx);
#pragma unroll
        for (int r = 0; r < 4; r++) {
            float4 h4;
            h4.x = gelu_exact(ha[r].x + bb1.x);
            h4.y = gelu_exact(ha[r].y + bb1.y);
            h4.z = gelu_exact(ha[r].z + bb1.z);
            h4.w = gelu_exact(ha[r].w + bb1.w);
            *(float4*)&hs[(my * 4 + r) * BH + hx * 4] = h4;
        }
        __syncthreads();

        // stage W2 chunk: ws[j*D + d] = W2e[hc + j][d]  (contiguous copy)
        {
            const float4* src = (const float4*)(W2e + (size_t)hc * D);
            float4* dst = (float4*)ws;
            for (int i = t; i < BH * D / 4; i += THREADS) dst[i] = src[i];
        }
        __syncthreads();

        // GEMM2: yacc[16 tokens][4 d] += hs @ W2chunk
        for (int hh = 0; hh < BH; hh++) {
            float4 w = *(const float4*)&ws[hh * D + tx * 4];
#pragma unroll
            for (int k = 0; k < 16; k++) {
                float hv = hs[(ty + 4 * k) * BH + hh];
                yacc[k].x += hv * w.x;
                yacc[k].y += hv * w.y;
                yacc[k].z += hv * w.z;
                yacc[k].w += hv * w.w;
            }
        }
    }

    // epilogue: out[n] += combine_w * (y + b2)
    float4 bb2 = ((const float4*)(b2 + e * D))[tx];
#pragma unroll
    for (int k = 0; k < 16; k++) {
        int m = ty + 4 * k;
        float w = swgt[m];
        if (w != 0.f) {
            float* o = out + (size_t)stok[m] * D + tx * 4;
            atomicAdd(o + 0, w * (yacc[k].x + bb2.x));
            atomicAdd(o + 1, w * (yacc[k].y + bb2.y));
            atomicAdd(o + 2, w * (yacc[k].z + bb2.z));
            atomicAdd(o + 3, w * (yacc[k].w + bb2.w));
        }
    }
}

// --------------------------------- launch --------------------------------
extern "C" void kernel_launch(void* const* d_in, const int* in_sizes, int n_in,
                              void* d_out, int out_size) {
    const float* x    = (const float*)d_in[0];
    const float* grad = (const float*)d_in[1];
    const float* Wr   = (const float*)d_in[2];
    const float* br   = (const float*)d_in[3];
    const float* W1   = (const float*)d_in[4];
    const float* b1   = (const float*)d_in[5];
    const float* W2   = (const float*)d_in[6];
    const float* b2   = (const float*)d_in[7];

    float* out   = (float*)d_out;                       // [N, D]
    float* probs = (float*)d_out + (size_t)N_TOK * D;   // [N, E]

    static int smem_set = 0;
    const int smem_bytes = (BM * D + BH * D + BM * BH) * 4 + BM * 8;
    if (!smem_set) {
        cudaFuncSetAttribute(expert_kernel,
                             cudaFuncAttributeMaxDynamicSharedMemorySize, smem_bytes);
        smem_set = 1;
    }

    // 1) zero out-region + counters
    init_kernel<<<(N_TOK * D / 4 + 255) / 256, 256>>>(out);
    // 2) router (1 warp per token)
    router_kernel<<<N_TOK / 8, 256>>>(x, grad, Wr, br, probs);
    // 3) grouped expert MLP (grid covers worst-case skew; empty tiles return)
    dim3 grid(N_TOK / BM, E);
    expert_kernel<<<grid, THREADS, smem_bytes>>>(x, W1, b1, W2, b2, out);
}

// round 3
// speedup vs baseline: 2.8198x; 2.8198x over previous
#include <cuda_runtime.h>
#include <cuda_bf16.h>
#include <math.h>
#include <stdint.h>

// ------------------------- problem constants -------------------------
#define N_TOK 32768
#define D     256
#define E     8
#define H     1024

#define BM 128          // tokens per GEMM CTA
#define BN 128          // output cols per GEMM CTA
#define KC 64           // K-chunk staged in smem
#define THREADS 256     // 8 warps: 2 (m) x 4 (n); warp tile 64x32

// smem layout (bytes): padded bf16 tiles, row stride 72 elems = 144 B
#define SSTRIDE 144
#define SA_HI 0
#define SA_LO 18432
#define SB_HI 36864
#define SB_LO 55296
#define SMETA 73728     // stok[128] int | srow[128] int | swgt[128] float
#define SMEM_BYTES (SMETA + 1536)

// ------------------------- static scratch -----------------------------
__device__ int            g_cnt[E];
__device__ int            g_tok[E * N_TOK];
__device__ int            g_row[E * N_TOK];     // h-row = token*2 + which
__device__ float          g_wgt[E * N_TOK];
__device__ __nv_bfloat16  g_xh[N_TOK * D];
__device__ __nv_bfloat16  g_xl[N_TOK * D];
__device__ __nv_bfloat16  g_w1h[E * H * D];     // [e][n=H][k=D]
__device__ __nv_bfloat16  g_w1l[E * H * D];
__device__ __nv_bfloat16  g_w2h[E * D * H];     // [e][n=D][k=H]
__device__ __nv_bfloat16  g_w2l[E * D * H];
__device__ __nv_bfloat16  g_hh[2 * N_TOK * H];  // gelu hidden, hi
__device__ __nv_bfloat16  g_hl[2 * N_TOK * H];  // gelu hidden, lo

// ------------------------- small helpers ------------------------------
__device__ __forceinline__ uint32_t smem_u32(const void* p) {
    uint32_t a;
    asm("{ .reg .u64 t; cvta.to.shared.u64 t, %1; cvt.u32.u64 %0, t; }"
        : "=r"(a) : "l"(p));
    return a;
}
__device__ __forceinline__ void ldm4(uint32_t* r, uint32_t addr) {
    asm volatile("ldmatrix.sync.aligned.m8n8.x4.shared.b16 {%0,%1,%2,%3}, [%4];"
                 : "=r"(r[0]), "=r"(r[1]), "=r"(r[2]), "=r"(r[3]) : "r"(addr));
}
__device__ __forceinline__ void mma16816(float* c, const uint32_t* a,
                                         uint32_t b0, uint32_t b1) {
    asm volatile("mma.sync.aligned.m16n8k16.row.col.f32.bf16.bf16.f32 "
                 "{%0,%1,%2,%3}, {%4,%5,%6,%7}, {%8,%9}, {%0,%1,%2,%3};"
                 : "+f"(c[0]), "+f"(c[1]), "+f"(c[2]), "+f"(c[3])
                 : "r"(a[0]), "r"(a[1]), "r"(a[2]), "r"(a[3]), "r"(b0), "r"(b1));
}
__device__ __forceinline__ float gelu_exact(float v) {
    return 0.5f * v * (1.f + erff(v * 0.70710678118654752f));
}

// ------------------------- prep kernels -------------------------------
__global__ void init_kernel(float* __restrict__ out) {
    int i = blockIdx.x * blockDim.x + threadIdx.x;
    if (i < (N_TOK * D) / 4) ((float4*)out)[i] = make_float4(0.f, 0.f, 0.f, 0.f);
    if (i < E) g_cnt[i] = 0;
}

__global__ void xconvert_kernel(const float* __restrict__ x) {
    int i = blockIdx.x * blockDim.x + threadIdx.x;
    if (i >= (N_TOK * D) / 4) return;
    float4 v = ((const float4*)x)[i];
    __nv_bfloat16 h0 = __float2bfloat16_rn(v.x), h1 = __float2bfloat16_rn(v.y);
    __nv_bfloat16 h2 = __float2bfloat16_rn(v.z), h3 = __float2bfloat16_rn(v.w);
    __nv_bfloat16 l0 = __float2bfloat16_rn(v.x - __bfloat162float(h0));
    __nv_bfloat16 l1 = __float2bfloat16_rn(v.y - __bfloat162float(h1));
    __nv_bfloat16 l2 = __float2bfloat16_rn(v.z - __bfloat162float(h2));
    __nv_bfloat16 l3 = __float2bfloat16_rn(v.w - __bfloat162float(h3));
    __nv_bfloat162* ph = (__nv_bfloat162*)g_xh;
    __nv_bfloat162* pl = (__nv_bfloat162*)g_xl;
    __nv_bfloat162 a, b;
    a.x = h0; a.y = h1; b.x = h2; b.y = h3;
    ph[2 * i] = a; ph[2 * i + 1] = b;
    a.x = l0; a.y = l1; b.x = l2; b.y = l3;
    pl[2 * i] = a; pl[2 * i + 1] = b;
}

// W1 [E][k=D][n=H] -> g_w1h/l [E][n][k]
__global__ void w1t_kernel(const float* __restrict__ W1) {
    __shared__ float tile[32][33];
    int e = blockIdx.z;
    int nb = blockIdx.x * 32, kb = blockIdx.y * 32;
    int tx = threadIdx.x, ty = threadIdx.y;
    for (int r = ty; r < 32; r += 8)
        tile[r][tx] = W1[(size_t)e * D * H + (size_t)(kb + r) * H + nb + tx];
    __syncthreads();
    for (int r = ty; r < 32; r += 8) {
        float v = tile[tx][r];
        __nv_bfloat16 hi = __float2bfloat16_rn(v);
        __nv_bfloat16 lo = __float2bfloat16_rn(v - __bfloat162float(hi));
        size_t o = ((size_t)e * H + nb + r) * D + kb + tx;
        g_w1h[o] = hi; g_w1l[o] = lo;
    }
}

// W2 [E][k=H][n=D] -> g_w2h/l [E][n][k]
__global__ void w2t_kernel(const float* __restrict__ W2) {
    __shared__ float tile[32][33];
    int e = blockIdx.z;
    int nb = blockIdx.x * 32, kb = blockIdx.y * 32;
    int tx = threadIdx.x, ty = threadIdx.y;
    for (int r = ty; r < 32; r += 8)
        tile[r][tx] = W2[(size_t)e * H * D + (size_t)(kb + r) * D + nb + tx];
    __syncthreads();
    for (int r = ty; r < 32; r += 8) {
        float v = tile[tx][r];
        __nv_bfloat16 hi = __float2bfloat16_rn(v);
        __nv_bfloat16 lo = __float2bfloat16_rn(v - __bfloat162float(hi));
        size_t o = ((size_t)e * D + nb + r) * H + kb + tx;
        g_w2h[o] = hi; g_w2l[o] = lo;
    }
}

// ------------------------- router -------------------------------------
__global__ void router_kernel(const float* __restrict__ x,
                              const float* __restrict__ grad,
                              const float* __restrict__ Wr,
                              const float* __restrict__ br,
                              float* __restrict__ probs_out) {
    int warp = (blockIdx.x * blockDim.x + threadIdx.x) >> 5;
    int lane = threadIdx.x & 31;
    if (warp >= N_TOK) return;
    int n = warp;

    float acc[E];
#pragma unroll
    for (int e = 0; e < E; e++) acc[e] = 0.f;
    const float* xr = x + (size_t)n * D;
    for (int d = lane; d < D; d += 32) {
        float xv = xr[d];
        const float* wrow = Wr + d * E;
#pragma unroll
        for (int e = 0; e < E; e++) acc[e] += xv * wrow[e];
    }
#pragma unroll
    for (int e = 0; e < E; e++)
#pragma unroll
        for (int off = 16; off > 0; off >>= 1)
            acc[e] += __shfl_xor_sync(0xffffffffu, acc[e], off);

    if (lane == 0) {
        float g = grad[n];
        const float* wg = Wr + D * E;
        float p[E]; float mx = -1e30f;
#pragma unroll
        for (int e = 0; e < E; e++) { p[e] = acc[e] + g * wg[e] + br[e]; mx = fmaxf(mx, p[e]); }
        float s = 0.f;
#pragma unroll
        for (int e = 0; e < E; e++) { p[e] = expf(p[e] - mx); s += p[e]; }
        float inv = 1.f / s;
#pragma unroll
        for (int e = 0; e < E; e++) { p[e] *= inv; probs_out[n * E + e] = p[e]; }

        int i1 = 0; float v1 = p[0];
#pragma unroll
        for (int e = 1; e < E; e++) if (p[e] > v1) { v1 = p[e]; i1 = e; }
        int i2 = -1; float v2 = -1.f;
#pragma unroll
        for (int e = 0; e < E; e++) if (e != i1 && p[e] > v2) { v2 = p[e]; i2 = e; }

        int s1 = atomicAdd(&g_cnt[i1], 1);
        g_tok[i1 * N_TOK + s1] = n; g_wgt[i1 * N_TOK + s1] = v1;
        g_row[i1 * N_TOK + s1] = 2 * n;
        int s2 = atomicAdd(&g_cnt[i2], 1);
        g_tok[i2 * N_TOK + s2] = n; g_wgt[i2 * N_TOK + s2] = v2;
        g_row[i2 * N_TOK + s2] = 2 * n + 1;
    }
}

// ---------------- shared tile-compute core (hi/lo x3 mma) --------------
// Computes acc[4][4][4] over one staged KC=64 chunk. Warp (wm, wn).
__device__ __forceinline__ void tile_mma(uint32_t su, int wm, int wn, int l,
                                         float acc[4][4][4]) {
#pragma unroll
    for (int k16 = 0; k16 < KC / 16; k16++) {
        int k0 = k16 * 16;
        int arow = wm * 64 + (l & 15);
        int acol = (k0 + ((l >> 4) & 1) * 8) * 2;
        int brow = wn * 32 + (l & 7) + ((l >> 4) & 1) * 8;
        int bcol = (k0 + ((l >> 3) & 1) * 8) * 2;

        uint32_t ah[4][4], bh[2][4];
#pragma unroll
        for (int mi = 0; mi < 4; mi++)
            ldm4(ah[mi], su + SA_HI + (arow + mi * 16) * SSTRIDE + acol);
#pragma unroll
        for (int nh = 0; nh < 2; nh++)
            ldm4(bh[nh], su + SB_HI + (brow + nh * 16) * SSTRIDE + bcol);
        // pass 1: hi * hi
#pragma unroll
        for (int mi = 0; mi < 4; mi++)
#pragma unroll
            for (int ni = 0; ni < 4; ni++)
                mma16816(acc[mi][ni], ah[mi],
                         bh[ni >> 1][(ni & 1) * 2], bh[ni >> 1][(ni & 1) * 2 + 1]);
        // pass 2: hi * lo
        {
            uint32_t bl[2][4];
#pragma unroll
            for (int nh = 0; nh < 2; nh++)
                ldm4(bl[nh], su + SB_LO + (brow + nh * 16) * SSTRIDE + bcol);
#pragma unroll
            for (int mi = 0; mi < 4; mi++)
#pragma unroll
                for (int ni = 0; ni < 4; ni++)
                    mma16816(acc[mi][ni], ah[mi],
                             bl[ni >> 1][(ni & 1) * 2], bl[ni >> 1][(ni & 1) * 2 + 1]);
        }
        // pass 3: lo * hi
        {
            uint32_t al[4][4];
#pragma unroll
            for (int mi = 0; mi < 4; mi++)
                ldm4(al[mi], su + SA_LO + (arow + mi * 16) * SSTRIDE + acol);
#pragma unroll
            for (int mi = 0; mi < 4; mi++)
#pragma unroll
                for (int ni = 0; ni < 4; ni++)
                    mma16816(acc[mi][ni], al[mi],
                             bh[ni >> 1][(ni & 1) * 2], bh[ni >> 1][(ni & 1) * 2 + 1]);
        }
    }
}

// ------------------------- GEMM1: h = gelu(x W1 + b1) ------------------
__global__ void __launch_bounds__(THREADS, 2) gemm1_kernel(const float* __restrict__ b1) {
    int e = blockIdx.z;
    int cnt = g_cnt[e];
    int base = blockIdx.x * BM;
    if (base >= cnt) return;
    int nb = blockIdx.y * BN;

    extern __shared__ char smem[];
    const uint32_t su = smem_u32(smem);
    int*   stok = (int*)(smem + SMETA);
    int*   srow = (int*)(smem + SMETA + 512);

    int t = threadIdx.x;
    int wid = t >> 5, l = t & 31;
    int wm = wid >> 2, wn = wid & 3;

    if (t < BM) {
        int idx = base + t;
        stok[t] = (idx < cnt) ? g_tok[e * N_TOK + idx] : 0;
        srow[t] = (idx < cnt) ? g_row[e * N_TOK + idx] : -1;
    }
    __syncthreads();

    float acc[4][4][4];
#pragma unroll
    for (int mi = 0; mi < 4; mi++)
#pragma unroll
        for (int ni = 0; ni < 4; ni++)
#pragma unroll
            for (int c = 0; c < 4; c++) acc[mi][ni][c] = 0.f;

    for (int kb = 0; kb < D; kb += KC) {
        // stage A (x gather) and B (W1) tiles, hi+lo
        for (int i = t; i < BM * (KC / 8); i += THREADS) {
            int row = i >> 3, q = i & 7;
            uint32_t doff = row * SSTRIDE + q * 16;
            size_t asrc = (size_t)stok[row] * D + kb + q * 8;
            size_t bsrc = ((size_t)(e * H + nb + row)) * D + kb + q * 8;
            *(uint4*)(smem + SA_HI + doff) = *(const uint4*)(g_xh + asrc);
            *(uint4*)(smem + SA_LO + doff) = *(const uint4*)(g_xl + asrc);
            *(uint4*)(smem + SB_HI + doff) = *(const uint4*)(g_w1h + bsrc);
            *(uint4*)(smem + SB_LO + doff) = *(const uint4*)(g_w1l + bsrc);
        }
        __syncthreads();
        tile_mma(su, wm, wn, l, acc);
        __syncthreads();
    }

    // epilogue: bias + gelu + hi/lo split -> g_hh/g_hl
    const float* b1e = b1 + e * H;
#pragma unroll
    for (int mi = 0; mi < 4; mi++) {
        int m0 = wm * 64 + mi * 16 + (l >> 2);
        int r0 = srow[m0], r1 = srow[m0 + 8];
#pragma unroll
        for (int ni = 0; ni < 4; ni++) {
            int col = nb + wn * 32 + ni * 8 + (l & 3) * 2;
            float ba = b1e[col], bb = b1e[col + 1];
#pragma unroll
            for (int half = 0; half < 2; half++) {
                int r = half ? r1 : r0;
                if (r < 0) continue;
                float g0 = gelu_exact(acc[mi][ni][half * 2 + 0] + ba);
                float g1 = gelu_exact(acc[mi][ni][half * 2 + 1] + bb);
                __nv_bfloat16 h0 = __float2bfloat16_rn(g0);
                __nv_bfloat16 h1 = __float2bfloat16_rn(g1);
                __nv_bfloat16 l0 = __float2bfloat16_rn(g0 - __bfloat162float(h0));
                __nv_bfloat16 l1 = __float2bfloat16_rn(g1 - __bfloat162float(h1));
                __nv_bfloat162 hp, lp;
                hp.x = h0; hp.y = h1; lp.x = l0; lp.y = l1;
                *(__nv_bfloat162*)(g_hh + (size_t)r * H + col) = hp;
                *(__nv_bfloat162*)(g_hl + (size_t)r * H + col) = lp;
            }
        }
    }
}

// ------------------------- GEMM2: out += w * (h W2 + b2) ---------------
__global__ void __launch_bounds__(THREADS, 2) gemm2_kernel(const float* __restrict__ b2,
                                                           float* __restrict__ out) {
    int e = blockIdx.z;
    int cnt = g_cnt[e];
    int base = blockIdx.x * BM;
    if (base >= cnt) return;
    int nb = blockIdx.y * BN;

    extern __shared__ char smem[];
    const uint32_t su = smem_u32(smem);
    int*   stok = (int*)(smem + SMETA);
    int*   srow = (int*)(smem + SMETA + 512);
    float* swgt = (float*)(smem + SMETA + 1024);

    int t = threadIdx.x;
    int wid = t >> 5, l = t & 31;
    int wm = wid >> 2, wn = wid & 3;

    if (t < BM) {
        int idx = base + t;
        stok[t] = (idx < cnt) ? g_tok[e * N_TOK + idx] : 0;
        srow[t] = (idx < cnt) ? g_row[e * N_TOK + idx] : 0;
        swgt[t] = (idx < cnt) ? g_wgt[e * N_TOK + idx] : 0.f;
    }
    __syncthreads();

    float acc[4][4][4];
#pragma unroll
    for (int mi = 0; mi < 4; mi++)
#pragma unroll
        for (int ni = 0; ni < 4; ni++)
#pragma unroll
            for (int c = 0; c < 4; c++) acc[mi][ni][c] = 0.f;

    for (int kb = 0; kb < H; kb += KC) {
        for (int i = t; i < BM * (KC / 8); i += THREADS) {
            int row = i >> 3, q = i & 7;
            uint32_t doff = row * SSTRIDE + q * 16;
            size_t asrc = (size_t)srow[row] * H + kb + q * 8;
            size_t bsrc = ((size_t)(e * D + nb + row)) * H + kb + q * 8;
            *(uint4*)(smem + SA_HI + doff) = *(const uint4*)(g_hh + asrc);
            *(uint4*)(smem + SA_LO + doff) = *(const uint4*)(g_hl + asrc);
            *(uint4*)(smem + SB_HI + doff) = *(const uint4*)(g_w2h + bsrc);
            *(uint4*)(smem + SB_LO + doff) = *(const uint4*)(g_w2l + bsrc);
        }
        __syncthreads();
        tile_mma(su, wm, wn, l, acc);
        __syncthreads();
    }

    // epilogue: out[token] += w * (acc + b2)
    const float* b2e = b2 + e * D;
#pragma unroll
    for (int mi = 0; mi < 4; mi++) {
        int m0 = wm * 64 + mi * 16 + (l >> 2);
#pragma unroll
        for (int half = 0; half < 2; half++) {
            int m = m0 + half * 8;
            float w = swgt[m];
            if (w == 0.f) continue;
            int tok = stok[m];
            float* op = out + (size_t)tok * D;
#pragma unroll
            for (int ni = 0; ni < 4; ni++) {
                int col = nb + wn * 32 + ni * 8 + (l & 3) * 2;
                atomicAdd(op + col,     w * (acc[mi][ni][half * 2 + 0] + b2e[col]));
                atomicAdd(op + col + 1, w * (acc[mi][ni][half * 2 + 1] + b2e[col + 1]));
            }
        }
    }
}

// --------------------------------- launch --------------------------------
extern "C" void kernel_launch(void* const* d_in, const int* in_sizes, int n_in,
                              void* d_out, int out_size) {
    const float* x    = (const float*)d_in[0];
    const float* grad = (const float*)d_in[1];
    const float* Wr   = (const float*)d_in[2];
    const float* br   = (const float*)d_in[3];
    const float* W1   = (const float*)d_in[4];
    const float* b1   = (const float*)d_in[5];
    const float* W2   = (const float*)d_in[6];
    const float* b2   = (const float*)d_in[7];

    float* out   = (float*)d_out;                       // [N, D]
    float* probs = (float*)d_out + (size_t)N_TOK * D;   // [N, E]

    static int attr_set = 0;
    if (!attr_set) {
        cudaFuncSetAttribute(gemm1_kernel,
                             cudaFuncAttributeMaxDynamicSharedMemorySize, SMEM_BYTES);
        cudaFuncSetAttribute(gemm2_kernel,
                             cudaFuncAttributeMaxDynamicSharedMemorySize, SMEM_BYTES);
        attr_set = 1;
    }

    init_kernel<<<(N_TOK * D / 4 + 255) / 256, 256>>>(out);
    xconvert_kernel<<<(N_TOK * D / 4 + 255) / 256, 256>>>(x);
    {
        dim3 g(H / 32, D / 32, E), b(32, 8);
        w1t_kernel<<<g, b>>>(W1);
    }
    {
        dim3 g(D / 32, H / 32, E), b(32, 8);
        w2t_kernel<<<g, b>>>(W2);
    }
    router_kernel<<<N_TOK / 8, 256>>>(x, grad, Wr, br, probs);
    {
        dim3 grid(N_TOK / BM, H / BN, E);   // (256, 8, 8)
        gemm1_kernel<<<grid, THREADS, SMEM_BYTES>>>(b1);
    }
    {
        dim3 grid(N_TOK / BM, D / BN, E);   // (256, 2, 8)
        gemm2_kernel<<<grid, THREADS, SMEM_BYTES>>>(b2, out);
    }
}

// round 5
// speedup vs baseline: 3.0821x; 1.0930x over previous
#include <cuda_runtime.h>
#include <cuda_bf16.h>
#include <math.h>
#include <stdint.h>

// ------------------------- problem constants -------------------------
#define N_TOK 32768
#define D     256
#define E     8
#define H     1024

#define BM 128          // tokens per GEMM CTA
#define BN 128          // output cols per GEMM CTA
#define KC 32           // K-chunk staged per pipeline stage
#define THREADS 256     // 8 warps: 2 (m) x 4 (n); warp tile 64x32

// smem: per stage 4 tiles (A_hi, A_lo, B_hi, B_lo), row stride 80 B
#define SSTRIDE    80
#define TILE_BYTES (128 * SSTRIDE)          // 10240
#define T_AHI 0
#define T_ALO (1 * TILE_BYTES)
#define T_BHI (2 * TILE_BYTES)
#define T_BLO (3 * TILE_BYTES)
#define STAGE_BYTES (4 * TILE_BYTES)        // 40960
#define SMETA (2 * STAGE_BYTES)             // 81920
#define SMEM_BYTES (SMETA + 1536)

// ------------------------- static scratch -----------------------------
__device__ int            g_cnt[E];
__device__ int            g_tok[E * N_TOK];
__device__ int            g_row[E * N_TOK];     // h-row = token*2 + slot
__device__ float          g_wgt[E * N_TOK];
__device__ __nv_bfloat16  g_xh[N_TOK * D];
__device__ __nv_bfloat16  g_xl[N_TOK * D];
__device__ __nv_bfloat16  g_w1h[E * H * D];     // [e][n=H][k=D]
__device__ __nv_bfloat16  g_w1l[E * H * D];
__device__ __nv_bfloat16  g_w2h[E * D * H];     // [e][n=D][k=H]
__device__ __nv_bfloat16  g_w2l[E * D * H];
__device__ __nv_bfloat16  g_hh[2 * N_TOK * H];  // gelu hidden, hi
__device__ __nv_bfloat16  g_hl[2 * N_TOK * H];  // gelu hidden, lo

// ------------------------- small helpers ------------------------------
__device__ __forceinline__ uint32_t smem_u32(const void* p) {
    uint32_t a;
    asm("{ .reg .u64 t; cvta.to.shared.u64 t, %1; cvt.u32.u64 %0, t; }"
        : "=r"(a) : "l"(p));
    return a;
}
__device__ __forceinline__ void ldm4(uint32_t* r, uint32_t addr) {
    asm volatile("ldmatrix.sync.aligned.m8n8.x4.shared.b16 {%0,%1,%2,%3}, [%4];"
                 : "=r"(r[0]), "=r"(r[1]), "=r"(r[2]), "=r"(r[3]) : "r"(addr));
}
__device__ __forceinline__ void mma16816(float* c, const uint32_t* a,
                                         uint32_t b0, uint32_t b1) {
    asm volatile("mma.sync.aligned.m16n8k16.row.col.f32.bf16.bf16.f32 "
                 "{%0,%1,%2,%3}, {%4,%5,%6,%7}, {%8,%9}, {%0,%1,%2,%3};"
                 : "+f"(c[0]), "+f"(c[1]), "+f"(c[2]), "+f"(c[3])
                 : "r"(a[0]), "r"(a[1]), "r"(a[2]), "r"(a[3]), "r"(b0), "r"(b1));
}
__device__ __forceinline__ void cpa16(uint32_t dst, const void* src) {
    asm volatile("cp.async.cg.shared.global [%0], [%1], 16;" :: "r"(dst), "l"(src));
}
#define CP_COMMIT() asm volatile("cp.async.commit_group;" ::: "memory")
#define CP_WAIT(n)  asm volatile("cp.async.wait_group %0;" :: "n"(n) : "memory")

__device__ __forceinline__ float gelu_exact(float v) {
    return 0.5f * v * (1.f + erff(v * 0.70710678118654752f));
}

// ------------------------- prep kernels -------------------------------
// zero out + counters, and split x into bf16 hi/lo — one pass
__global__ void prep_x_kernel(const float* __restrict__ x, float* __restrict__ out) {
    int i = blockIdx.x * blockDim.x + threadIdx.x;
    if (i < E) g_cnt[i] = 0;
    if (i >= (N_TOK * D) / 4) return;
    ((float4*)out)[i] = make_float4(0.f, 0.f, 0.f, 0.f);
    float4 v = ((const float4*)x)[i];
    __nv_bfloat16 h0 = __float2bfloat16_rn(v.x), h1 = __float2bfloat16_rn(v.y);
    __nv_bfloat16 h2 = __float2bfloat16_rn(v.z), h3 = __float2bfloat16_rn(v.w);
    __nv_bfloat16 l0 = __float2bfloat16_rn(v.x - __bfloat162float(h0));
    __nv_bfloat16 l1 = __float2bfloat16_rn(v.y - __bfloat162float(h1));
    __nv_bfloat16 l2 = __float2bfloat16_rn(v.z - __bfloat162float(h2));
    __nv_bfloat16 l3 = __float2bfloat16_rn(v.w - __bfloat162float(h3));
    __nv_bfloat162* ph = (__nv_bfloat162*)g_xh;
    __nv_bfloat162* pl = (__nv_bfloat162*)g_xl;
    __nv_bfloat162 a, b;
    a.x = h0; a.y = h1; b.x = h2; b.y = h3;
    ph[2 * i] = a; ph[2 * i + 1] = b;
    a.x = l0; a.y = l1; b.x = l2; b.y = l3;
    pl[2 * i] = a; pl[2 * i + 1] = b;
}

// transpose + split W1: [E][k=D][n=H] -> g_w1h/l [E][n][k]
__global__ void w1t_kernel(const float* __restrict__ W1) {
    __shared__ float tile[32][33];
    int e = blockIdx.z;
    int nb = blockIdx.x * 32, kb = blockIdx.y * 32;
    int tx = threadIdx.x, ty = threadIdx.y;
    for (int r = ty; r < 32; r += 8)
        tile[r][tx] = W1[(size_t)e * D * H + (size_t)(kb + r) * H + nb + tx];
    __syncthreads();
    for (int r = ty; r < 32; r += 8) {
        float v = tile[tx][r];
        __nv_bfloat16 hi = __float2bfloat16_rn(v);
        __nv_bfloat16 lo = __float2bfloat16_rn(v - __bfloat162float(hi));
        size_t o = ((size_t)e * H + nb + r) * D + kb + tx;
        g_w1h[o] = hi; g_w1l[o] = lo;
    }
}

// transpose + split W2: [E][k=H][n=D] -> g_w2h/l [E][n][k]
__global__ void w2t_kernel(const float* __restrict__ W2) {
    __shared__ float tile[32][33];
    int e = blockIdx.z;
    int nb = blockIdx.x * 32, kb = blockIdx.y * 32;
    int tx = threadIdx.x, ty = threadIdx.y;
    for (int r = ty; r < 32; r += 8)
        tile[r][tx] = W2[(size_t)e * H * D + (size_t)(kb + r) * D + nb + tx];
    __syncthreads();
    for (int r = ty; r < 32; r += 8) {
        float v = tile[tx][r];
        __nv_bfloat16 hi = __float2bfloat16_rn(v);
        __nv_bfloat16 lo = __float2bfloat16_rn(v - __bfloat162float(hi));
        size_t o = ((size_t)e * D + nb + r) * H + kb + tx;
        g_w2h[o] = hi; g_w2l[o] = lo;
    }
}

// ------------------------- router -------------------------------------
__global__ void router_kernel(const float* __restrict__ x,
                              const float* __restrict__ grad,
                              const float* __restrict__ Wr,
                              const float* __restrict__ br,
                              float* __restrict__ probs_out) {
    int warp = (blockIdx.x * blockDim.x + threadIdx.x) >> 5;
    int lane = threadIdx.x & 31;
    if (warp >= N_TOK) return;
    int n = warp;

    float acc[E];
#pragma unroll
    for (int e = 0; e < E; e++) acc[e] = 0.f;
    const float* xr = x + (size_t)n * D;
    for (int d = lane; d < D; d += 32) {
        float xv = xr[d];
        const float* wrow = Wr + d * E;
#pragma unroll
        for (int e = 0; e < E; e++) acc[e] += xv * wrow[e];
    }
#pragma unroll
    for (int e = 0; e < E; e++)
#pragma unroll
        for (int off = 16; off > 0; off >>= 1)
            acc[e] += __shfl_xor_sync(0xffffffffu, acc[e], off);

    if (lane == 0) {
        float g = grad[n];
        const float* wg = Wr + D * E;
        float p[E]; float mx = -1e30f;
#pragma unroll
        for (int e = 0; e < E; e++) { p[e] = acc[e] + g * wg[e] + br[e]; mx = fmaxf(mx, p[e]); }
        float s = 0.f;
#pragma unroll
        for (int e = 0; e < E; e++) { p[e] = expf(p[e] - mx); s += p[e]; }
        float inv = 1.f / s;
#pragma unroll
        for (int e = 0; e < E; e++) { p[e] *= inv; probs_out[n * E + e] = p[e]; }

        int i1 = 0; float v1 = p[0];
#pragma unroll
        for (int e = 1; e < E; e++) if (p[e] > v1) { v1 = p[e]; i1 = e; }
        int i2 = -1; float v2 = -1.f;
#pragma unroll
        for (int e = 0; e < E; e++) if (e != i1 && p[e] > v2) { v2 = p[e]; i2 = e; }

        int s1 = atomicAdd(&g_cnt[i1], 1);
        g_tok[i1 * N_TOK + s1] = n; g_wgt[i1 * N_TOK + s1] = v1;
        g_row[i1 * N_TOK + s1] = 2 * n;
        int s2 = atomicAdd(&g_cnt[i2], 1);
        g_tok[i2 * N_TOK + s2] = n; g_wgt[i2 * N_TOK + s2] = v2;
        g_row[i2 * N_TOK + s2] = 2 * n + 1;
    }
}

// ---------------- tile compute: hi/lo x3 mma over one KC=32 chunk ------
__device__ __forceinline__ void tile_mma(uint32_t sb, int wm, int wn, int l,
                                         float acc[4][4][4]) {
#pragma unroll
    for (int k16 = 0; k16 < KC / 16; k16++) {
        int k0 = k16 * 16;
        int arow = wm * 64 + (l & 15);
        int acol = (k0 + ((l >> 4) & 1) * 8) * 2;
        int brow = wn * 32 + (l & 7) + ((l >> 4) & 1) * 8;
        int bcol = (k0 + ((l >> 3) & 1) * 8) * 2;

        uint32_t ah[4][4], bh[2][4];
#pragma unroll
        for (int mi = 0; mi < 4; mi++)
            ldm4(ah[mi], sb + T_AHI + (arow + mi * 16) * SSTRIDE + acol);
#pragma unroll
        for (int nh = 0; nh < 2; nh++)
            ldm4(bh[nh], sb + T_BHI + (brow + nh * 16) * SSTRIDE + bcol);
#pragma unroll
        for (int mi = 0; mi < 4; mi++)
#pragma unroll
            for (int ni = 0; ni < 4; ni++)
                mma16816(acc[mi][ni], ah[mi],
                         bh[ni >> 1][(ni & 1) * 2], bh[ni >> 1][(ni & 1) * 2 + 1]);
        {
            uint32_t bl[2][4];
#pragma unroll
            for (int nh = 0; nh < 2; nh++)
                ldm4(bl[nh], sb + T_BLO + (brow + nh * 16) * SSTRIDE + bcol);
#pragma unroll
            for (int mi = 0; mi < 4; mi++)
#pragma unroll
                for (int ni = 0; ni < 4; ni++)
                    mma16816(acc[mi][ni], ah[mi],
                             bl[ni >> 1][(ni & 1) * 2], bl[ni >> 1][(ni & 1) * 2 + 1]);
        }
        {
            uint32_t al[4][4];
#pragma unroll
            for (int mi = 0; mi < 4; mi++)
                ldm4(al[mi], sb + T_ALO + (arow + mi * 16) * SSTRIDE + acol);
#pragma unroll
            for (int mi = 0; mi < 4; mi++)
#pragma unroll
                for (int ni = 0; ni < 4; ni++)
                    mma16816(acc[mi][ni], al[mi],
                             bh[ni >> 1][(ni & 1) * 2], bh[ni >> 1][(ni & 1) * 2 + 1]);
        }
    }
}

// ---------------- staging: cp.async one KC chunk into stage buffer -----
__device__ __forceinline__ void stage_chunk(
    uint32_t sbuf, int t,
    const __nv_bfloat16* ah, const __nv_bfloat16* al, const int* arow_idx, int lda,
    const __nv_bfloat16* bh, const __nv_bfloat16* bl, size_t bbase, int ldb,
    int kb)
{
#pragma unroll
    for (int rep = 0; rep < 2; rep++) {
        int i = t + rep * THREADS;                 // 0..511
        int row = i >> 2, q = i & 3;
        uint32_t doff = row * SSTRIDE + q * 16;
        size_t aoff = (size_t)arow_idx[row] * lda + kb + q * 8;
        size_t boff = (bbase + row) * ldb + kb + q * 8;
        cpa16(sbuf + T_AHI + doff, ah + aoff);
        cpa16(sbuf + T_ALO + doff, al + aoff);
        cpa16(sbuf + T_BHI + doff, bh + boff);
        cpa16(sbuf + T_BLO + doff, bl + boff);
    }
}

// ------------------------- GEMM1: h = gelu(x W1 + b1) ------------------
__global__ void __launch_bounds__(THREADS, 2) gemm1_kernel(const float* __restrict__ b1) {
    int e = blockIdx.z;
    int cnt = g_cnt[e];
    int base = blockIdx.x * BM;
    if (base >= cnt) return;
    int nb = blockIdx.y * BN;

    extern __shared__ char smem[];
    const uint32_t su = smem_u32(smem);
    int* stok = (int*)(smem + SMETA);
    int* srow = (int*)(smem + SMETA + 512);

    int t = threadIdx.x;
    int wid = t >> 5, l = t & 31;
    int wm = wid >> 2, wn = wid & 3;

    if (t < BM) {
        int idx = base + t;
        stok[t] = (idx < cnt) ? g_tok[e * N_TOK + idx] : 0;
        srow[t] = (idx < cnt) ? g_row[e * N_TOK + idx] : -1;
    }
    __syncthreads();

    float acc[4][4][4];
#pragma unroll
    for (int mi = 0; mi < 4; mi++)
#pragma unroll
        for (int ni = 0; ni < 4; ni++)
#pragma unroll
            for (int c = 0; c < 4; c++) acc[mi][ni][c] = 0.f;

    size_t bbase = (size_t)e * H + nb;
    const int NK = D / KC;   // 8

    stage_chunk(su, t, g_xh, g_xl, stok, D, g_w1h, g_w1l, bbase, D, 0);
    CP_COMMIT();
#pragma unroll 1
    for (int k = 0; k < NK; k++) {
        if (k + 1 < NK) {
            stage_chunk(su + ((k + 1) & 1) * STAGE_BYTES, t,
                        g_xh, g_xl, stok, D, g_w1h, g_w1l, bbase, D, (k + 1) * KC);
            CP_COMMIT();
            CP_WAIT(1);
        } else {
            CP_WAIT(0);
        }
        __syncthreads();
        tile_mma(su + (k & 1) * STAGE_BYTES, wm, wn, l, acc);
        __syncthreads();
    }

    // epilogue: bias + gelu + hi/lo split -> g_hh/g_hl
    const float* b1e = b1 + e * H;
#pragma unroll
    for (int mi = 0; mi < 4; mi++) {
        int m0 = wm * 64 + mi * 16 + (l >> 2);
        int r0 = srow[m0], r1 = srow[m0 + 8];
#pragma unroll
        for (int ni = 0; ni < 4; ni++) {
            int col = nb + wn * 32 + ni * 8 + (l & 3) * 2;
            float ba = b1e[col], bb = b1e[col + 1];
#pragma unroll
            for (int half = 0; half < 2; half++) {
                int r = half ? r1 : r0;
                if (r < 0) continue;
                float g0 = gelu_exact(acc[mi][ni][half * 2 + 0] + ba);
                float g1 = gelu_exact(acc[mi][ni][half * 2 + 1] + bb);
                __nv_bfloat16 h0 = __float2bfloat16_rn(g0);
                __nv_bfloat16 h1 = __float2bfloat16_rn(g1);
                __nv_bfloat16 l0 = __float2bfloat16_rn(g0 - __bfloat162float(h0));
                __nv_bfloat16 l1 = __float2bfloat16_rn(g1 - __bfloat162float(h1));
                __nv_bfloat162 hp, lp;
                hp.x = h0; hp.y = h1; lp.x = l0; lp.y = l1;
                *(__nv_bfloat162*)(g_hh + (size_t)r * H + col) = hp;
                *(__nv_bfloat162*)(g_hl + (size_t)r * H + col) = lp;
            }
        }
    }
}

// ------------------------- GEMM2: out += w * (h W2 + b2) ---------------
__global__ void __launch_bounds__(THREADS, 2) gemm2_kernel(const float* __restrict__ b2,
                                                           float* __restrict__ out) {
    int e = blockIdx.z;
    int cnt = g_cnt[e];
    int base = blockIdx.x * BM;
    if (base >= cnt) return;
    int nb = blockIdx.y * BN;

    extern __shared__ char smem[];
    const uint32_t su = smem_u32(smem);
    int*   stok = (int*)(smem + SMETA);
    int*   srow = (int*)(smem + SMETA + 512);
    float* swgt = (float*)(smem + SMETA + 1024);

    int t = threadIdx.x;
    int wid = t >> 5, l = t & 31;
    int wm = wid >> 2, wn = wid & 3;

    if (t < BM) {
        int idx = base + t;
        stok[t] = (idx < cnt) ? g_tok[e * N_TOK + idx] : 0;
        srow[t] = (idx < cnt) ? g_row[e * N_TOK + idx] : 0;
        swgt[t] = (idx < cnt) ? g_wgt[e * N_TOK + idx] : 0.f;
    }
    __syncthreads();

    float acc[4][4][4];
#pragma unroll
    for (int mi = 0; mi < 4; mi++)
#pragma unroll
        for (int ni = 0; ni < 4; ni++)
#pragma unroll
            for (int c = 0; c < 4; c++) acc[mi][ni][c] = 0.f;

    size_t bbase = (size_t)e * D + nb;
    const int NK = H / KC;   // 32

    stage_chunk(su, t, g_hh, g_hl, srow, H, g_w2h, g_w2l, bbase, H, 0);
    CP_COMMIT();
#pragma unroll 1
    for (int k = 0; k < NK; k++) {
        if (k + 1 < NK) {
            stage_chunk(su + ((k + 1) & 1) * STAGE_BYTES, t,
                        g_hh, g_hl, srow, H, g_w2h, g_w2l, bbase, H, (k + 1) * KC);
            CP_COMMIT();
            CP_WAIT(1);
        } else {
            CP_WAIT(0);
        }
        __syncthreads();
        tile_mma(su + (k & 1) * STAGE_BYTES, wm, wn, l, acc);
        __syncthreads();
    }

    // epilogue: out[token] += w * (acc + b2)
    const float* b2e = b2 + e * D;
#pragma unroll
    for (int mi = 0; mi < 4; mi++) {
        int m0 = wm * 64 + mi * 16 + (l >> 2);
#pragma unroll
        for (int half = 0; half < 2; half++) {
            int m = m0 + half * 8;
            float w = swgt[m];
            if (w == 0.f) continue;
            int tok = stok[m];
            float* op = out + (size_t)tok * D;
#pragma unroll
            for (int ni = 0; ni < 4; ni++) {
                int col = nb + wn * 32 + ni * 8 + (l & 3) * 2;
                atomicAdd(op + col,     w * (acc[mi][ni][half * 2 + 0] + b2e[col]));
                atomicAdd(op + col + 1, w * (acc[mi][ni][half * 2 + 1] + b2e[col + 1]));
            }
        }
    }
}

// --------------------------------- launch --------------------------------
extern "C" void kernel_launch(void* const* d_in, const int* in_sizes, int n_in,
                              void* d_out, int out_size) {
    const float* x    = (const float*)d_in[0];
    const float* grad = (const float*)d_in[1];
    const float* Wr   = (const float*)d_in[2];
    const float* br   = (const float*)d_in[3];
    const float* W1   = (const float*)d_in[4];
    const float* b1   = (const float*)d_in[5];
    const float* W2   = (const float*)d_in[6];
    const float* b2   = (const float*)d_in[7];

    float* out   = (float*)d_out;                       // [N, D]
    float* probs = (float*)d_out + (size_t)N_TOK * D;   // [N, E]

    static int attr_set = 0;
    if (!attr_set) {
        cudaFuncSetAttribute(gemm1_kernel,
                             cudaFuncAttributeMaxDynamicSharedMemorySize, SMEM_BYTES);
        cudaFuncSetAttribute(gemm2_kernel,
                             cudaFuncAttributeMaxDynamicSharedMemorySize, SMEM_BYTES);
        attr_set = 1;
    }

    prep_x_kernel<<<(N_TOK * D / 4 + 255) / 256, 256>>>(x, out);
    {
        dim3 g(H / 32, D / 32, E), b(32, 8);   // W1: n over H, k over D
        w1t_kernel<<<g, b>>>(W1);
    }
    {
        dim3 g(D / 32, H / 32, E), b(32, 8);   // W2: n over D, k over H
        w2t_kernel<<<g, b>>>(W2);
    }
    router_kernel<<<N_TOK / 8, 256>>>(x, grad, Wr, br, probs);
    {
        dim3 grid(N_TOK / BM, H / BN, E);   // (256, 8, 8)
        gemm1_kernel<<<grid, THREADS, SMEM_BYTES>>>(b1);
    }
    {
        dim3 grid(N_TOK / BM, D / BN, E);   // (256, 2, 8)
        gemm2_kernel<<<grid, THREADS, SMEM_BYTES>>>(b2, out);
    }
}

// round 7
// speedup vs baseline: 3.2907x; 1.0677x over previous
#include <cuda_runtime.h>
#include <cuda_bf16.h>
#include <math.h>
#include <stdint.h>

// ------------------------- problem constants -------------------------
#define N_TOK 32768
#define D     256
#define E     8
#define H     1024

#define BM 128          // tokens per GEMM CTA
#define BN 128          // output cols per GEMM CTA
#define KC 32           // K-chunk staged per pipeline stage
#define THREADS 256     // 8 warps: 2 (m) x 4 (n); warp tile 64x32

// smem: per stage 4 tiles (A_hi, A_lo, B_hi, B_lo), row stride 80 B
#define SSTRIDE    80
#define TILE_BYTES (128 * SSTRIDE)          // 10240
#define T_AHI 0
#define T_ALO (1 * TILE_BYTES)
#define T_BHI (2 * TILE_BYTES)
#define T_BLO (3 * TILE_BYTES)
#define STAGE_BYTES (4 * TILE_BYTES)        // 40960
#define SMETA (2 * STAGE_BYTES)             // 81920
#define SMEM_BYTES (SMETA + 1536)

// ------------------------- static scratch -----------------------------
__device__ int            g_cnt[E];
__device__ int            g_tok[E * N_TOK];
__device__ int            g_row[E * N_TOK];     // h-row = token*2 + slot
__device__ float          g_wgt[E * N_TOK];
__device__ __nv_bfloat16  g_xh[N_TOK * D];
__device__ __nv_bfloat16  g_xl[N_TOK * D];
__device__ __nv_bfloat16  g_w1h[E * H * D];     // [e][n=H][k=D]
__device__ __nv_bfloat16  g_w1l[E * H * D];
__device__ __nv_bfloat16  g_w2h[E * D * H];     // [e][n=D][k=H]
__device__ __nv_bfloat16  g_w2l[E * D * H];
__device__ __nv_bfloat16  g_hh[2 * N_TOK * H];  // gelu hidden, hi
__device__ __nv_bfloat16  g_hl[2 * N_TOK * H];  // gelu hidden, lo

// ------------------------- small helpers ------------------------------
__device__ __forceinline__ uint32_t smem_u32(const void* p) {
    uint32_t a;
    asm("{ .reg .u64 t; cvta.to.shared.u64 t, %1; cvt.u32.u64 %0, t; }"
        : "=r"(a) : "l"(p));
    return a;
}
__device__ __forceinline__ void ldm4(uint32_t* r, uint32_t addr) {
    asm volatile("ldmatrix.sync.aligned.m8n8.x4.shared.b16 {%0,%1,%2,%3}, [%4];"
                 : "=r"(r[0]), "=r"(r[1]), "=r"(r[2]), "=r"(r[3]) : "r"(addr));
}
__device__ __forceinline__ void mma16816(float* c, const uint32_t* a,
                                         uint32_t b0, uint32_t b1) {
    asm volatile("mma.sync.aligned.m16n8k16.row.col.f32.bf16.bf16.f32 "
                 "{%0,%1,%2,%3}, {%4,%5,%6,%7}, {%8,%9}, {%0,%1,%2,%3};"
                 : "+f"(c[0]), "+f"(c[1]), "+f"(c[2]), "+f"(c[3])
                 : "r"(a[0]), "r"(a[1]), "r"(a[2]), "r"(a[3]), "r"(b0), "r"(b1));
}
__device__ __forceinline__ void cpa16(uint32_t dst, const void* src) {
    asm volatile("cp.async.cg.shared.global [%0], [%1], 16;" :: "r"(dst), "l"(src));
}
#define CP_COMMIT() asm volatile("cp.async.commit_group;" ::: "memory")
#define CP_WAIT(n)  asm volatile("cp.async.wait_group %0;" :: "n"(n) : "memory")

__device__ __forceinline__ float gelu_exact(float v) {
    return 0.5f * v * (1.f + erff(v * 0.70710678118654752f));
}

// ------------------------- prep kernels -------------------------------
// zero out + counters, and split x into bf16 hi/lo — one pass
__global__ void prep_x_kernel(const float* __restrict__ x, float* __restrict__ out) {
    int i = blockIdx.x * blockDim.x + threadIdx.x;
    if (i < E) g_cnt[i] = 0;
    if (i >= (N_TOK * D) / 4) return;
    ((float4*)out)[i] = make_float4(0.f, 0.f, 0.f, 0.f);
    float4 v = ((const float4*)x)[i];
    __nv_bfloat16 h0 = __float2bfloat16_rn(v.x), h1 = __float2bfloat16_rn(v.y);
    __nv_bfloat16 h2 = __float2bfloat16_rn(v.z), h3 = __float2bfloat16_rn(v.w);
    __nv_bfloat16 l0 = __float2bfloat16_rn(v.x - __bfloat162float(h0));
    __nv_bfloat16 l1 = __float2bfloat16_rn(v.y - __bfloat162float(h1));
    __nv_bfloat16 l2 = __float2bfloat16_rn(v.z - __bfloat162float(h2));
    __nv_bfloat16 l3 = __float2bfloat16_rn(v.w - __bfloat162float(h3));
    __nv_bfloat162* ph = (__nv_bfloat162*)g_xh;
    __nv_bfloat162* pl = (__nv_bfloat162*)g_xl;
    __nv_bfloat162 a, b;
    a.x = h0; a.y = h1; b.x = h2; b.y = h3;
    ph[2 * i] = a; ph[2 * i + 1] = b;
    a.x = l0; a.y = l1; b.x = l2; b.y = l3;
    pl[2 * i] = a; pl[2 * i + 1] = b;
}

// transpose + split W1: [E][k=D][n=H] -> g_w1h/l [E][n][k]
__global__ void w1t_kernel(const float* __restrict__ W1) {
    __shared__ float tile[32][33];
    int e = blockIdx.z;
    int nb = blockIdx.x * 32, kb = blockIdx.y * 32;
    int tx = threadIdx.x, ty = threadIdx.y;
    for (int r = ty; r < 32; r += 8)
        tile[r][tx] = W1[(size_t)e * D * H + (size_t)(kb + r) * H + nb + tx];
    __syncthreads();
    for (int r = ty; r < 32; r += 8) {
        float v = tile[tx][r];
        __nv_bfloat16 hi = __float2bfloat16_rn(v);
        __nv_bfloat16 lo = __float2bfloat16_rn(v - __bfloat162float(hi));
        size_t o = ((size_t)e * H + nb + r) * D + kb + tx;
        g_w1h[o] = hi; g_w1l[o] = lo;
    }
}

// transpose + split W2: [E][k=H][n=D] -> g_w2h/l [E][n][k]
__global__ void w2t_kernel(const float* __restrict__ W2) {
    __shared__ float tile[32][33];
    int e = blockIdx.z;
    int nb = blockIdx.x * 32, kb = blockIdx.y * 32;
    int tx = threadIdx.x, ty = threadIdx.y;
    for (int r = ty; r < 32; r += 8)
        tile[r][tx] = W2[(size_t)e * H * D + (size_t)(kb + r) * D + nb + tx];
    __syncthreads();
    for (int r = ty; r < 32; r += 8) {
        float v = tile[tx][r];
        __nv_bfloat16 hi = __float2bfloat16_rn(v);
        __nv_bfloat16 lo = __float2bfloat16_rn(v - __bfloat162float(hi));
        size_t o = ((size_t)e * D + nb + r) * H + kb + tx;
        g_w2h[o] = hi; g_w2l[o] = lo;
    }
}

// ------------------------- router (tiled SMEM) -------------------------
// 32 tokens per 256-thread CTA. Stage x tile + full Wr + br into SMEM;
// thread (tok, e) computes one logit from SMEM (broadcast reads only);
// then 32 threads do softmax / top-2 / scatter.
#define RT_TOK 32
#define RT_XS  260                         // padded stride (floats): banks differ per token
__global__ void __launch_bounds__(256) router_kernel(
    const float* __restrict__ x,
    const float* __restrict__ grad,
    const float* __restrict__ Wr,
    const float* __restrict__ br,
    float* __restrict__ probs_out)
{
    __shared__ float xs[RT_TOK * RT_XS];          // 33.3 KB
    __shared__ float wr[(D + 1) * E];             // 8.2 KB
    __shared__ float sbr[E];
    __shared__ float lg[RT_TOK * E];

    int t = threadIdx.x;
    int base = blockIdx.x * RT_TOK;

    // stage x tile: 32 rows x 64 float4, coalesced
    for (int i = t; i < RT_TOK * (D / 4); i += 256) {
        int row = i >> 6, c = i & 63;
        float4 v = ((const float4*)(x + (size_t)(base + row) * D))[c];
        float* dst = xs + row * RT_XS + c * 4;
        dst[0] = v.x; dst[1] = v.y; dst[2] = v.z; dst[3] = v.w;
    }
    // stage Wr (+grad row) and br
    for (int i = t; i < (D + 1) * E / 2; i += 256)
        ((float2*)wr)[i] = ((const float2*)Wr)[i];
    if (t < E) sbr[t] = br[t];
    __syncthreads();

    // one logit per thread: tok = t>>3, e = t&7
    {
        int tok = t >> 3, e = t & 7;
        const float* xr = xs + tok * RT_XS;
        float acc = 0.f;
#pragma unroll 8
        for (int d = 0; d < D; d++)
            acc = fmaf(xr[d], wr[d * E + e], acc);
        acc += grad[base + tok] * wr[D * E + e] + sbr[e];
        lg[tok * E + e] = acc;
    }
    __syncthreads();

    if (t < RT_TOK) {
        int n = base + t;
        float p[E]; float mx = -1e30f;
#pragma unroll
        for (int e = 0; e < E; e++) { p[e] = lg[t * E + e]; mx = fmaxf(mx, p[e]); }
        float s = 0.f;
#pragma unroll
        for (int e = 0; e < E; e++) { p[e] = expf(p[e] - mx); s += p[e]; }
        float inv = 1.f / s;
#pragma unroll
        for (int e = 0; e < E; e++) p[e] *= inv;
        float4* po = (float4*)(probs_out + (size_t)n * E);
        po[0] = make_float4(p[0], p[1], p[2], p[3]);
        po[1] = make_float4(p[4], p[5], p[6], p[7]);

        // top-2 (ties -> lowest index first, matching jax.lax.top_k)
        int i1 = 0; float v1 = p[0];
#pragma unroll
        for (int e = 1; e < E; e++) if (p[e] > v1) { v1 = p[e]; i1 = e; }
        int i2 = -1; float v2 = -1.f;
#pragma unroll
        for (int e = 0; e < E; e++) if (e != i1 && p[e] > v2) { v2 = p[e]; i2 = e; }

        int s1 = atomicAdd(&g_cnt[i1], 1);
        g_tok[i1 * N_TOK + s1] = n; g_wgt[i1 * N_TOK + s1] = v1;
        g_row[i1 * N_TOK + s1] = 2 * n;
        int s2 = atomicAdd(&g_cnt[i2], 1);
        g_tok[i2 * N_TOK + s2] = n; g_wgt[i2 * N_TOK + s2] = v2;
        g_row[i2 * N_TOK + s2] = 2 * n + 1;
    }
}

// ---------------- tile compute: hi/lo x3 mma over one KC=32 chunk ------
__device__ __forceinline__ void tile_mma(uint32_t sb, int wm, int wn, int l,
                                         float acc[4][4][4]) {
#pragma unroll
    for (int k16 = 0; k16 < KC / 16; k16++) {
        int k0 = k16 * 16;
        int arow = wm * 64 + (l & 15);
        int acol = (k0 + ((l >> 4) & 1) * 8) * 2;
        int brow = wn * 32 + (l & 7) + ((l >> 4) & 1) * 8;
        int bcol = (k0 + ((l >> 3) & 1) * 8) * 2;

        uint32_t ah[4][4], bh[2][4];
#pragma unroll
        for (int mi = 0; mi < 4; mi++)
            ldm4(ah[mi], sb + T_AHI + (arow + mi * 16) * SSTRIDE + acol);
#pragma unroll
        for (int nh = 0; nh < 2; nh++)
            ldm4(bh[nh], sb + T_BHI + (brow + nh * 16) * SSTRIDE + bcol);
#pragma unroll
        for (int mi = 0; mi < 4; mi++)
#pragma unroll
            for (int ni = 0; ni < 4; ni++)
                mma16816(acc[mi][ni], ah[mi],
                         bh[ni >> 1][(ni & 1) * 2], bh[ni >> 1][(ni & 1) * 2 + 1]);
        {
            uint32_t bl[2][4];
#pragma unroll
            for (int nh = 0; nh < 2; nh++)
                ldm4(bl[nh], sb + T_BLO + (brow + nh * 16) * SSTRIDE + bcol);
#pragma unroll
            for (int mi = 0; mi < 4; mi++)
#pragma unroll
                for (int ni = 0; ni < 4; ni++)
                    mma16816(acc[mi][ni], ah[mi],
                             bl[ni >> 1][(ni & 1) * 2], bl[ni >> 1][(ni & 1) * 2 + 1]);
        }
        {
            uint32_t al[4][4];
#pragma unroll
            for (int mi = 0; mi < 4; mi++)
                ldm4(al[mi], sb + T_ALO + (arow + mi * 16) * SSTRIDE + acol);
#pragma unroll
            for (int mi = 0; mi < 4; mi++)
#pragma unroll
                for (int ni = 0; ni < 4; ni++)
                    mma16816(acc[mi][ni], al[mi],
                             bh[ni >> 1][(ni & 1) * 2], bh[ni >> 1][(ni & 1) * 2 + 1]);
        }
    }
}

// ---------------- staging: cp.async one KC chunk into stage buffer -----
__device__ __forceinline__ void stage_chunk(
    uint32_t sbuf, int t,
    const __nv_bfloat16* ah, const __nv_bfloat16* al, const int* arow_idx, int lda,
    const __nv_bfloat16* bh, const __nv_bfloat16* bl, size_t bbase, int ldb,
    int kb)
{
#pragma unroll
    for (int rep = 0; rep < 2; rep++) {
        int i = t + rep * THREADS;                 // 0..511
        int row = i >> 2, q = i & 3;
        uint32_t doff = row * SSTRIDE + q * 16;
        size_t aoff = (size_t)arow_idx[row] * lda + kb + q * 8;
        size_t boff = (bbase + row) * ldb + kb + q * 8;
        cpa16(sbuf + T_AHI + doff, ah + aoff);
        cpa16(sbuf + T_ALO + doff, al + aoff);
        cpa16(sbuf + T_BHI + doff, bh + boff);
        cpa16(sbuf + T_BLO + doff, bl + boff);
    }
}

// ------------------------- GEMM1: h = gelu(x W1 + b1) ------------------
__global__ void __launch_bounds__(THREADS, 2) gemm1_kernel(const float* __restrict__ b1) {
    int e = blockIdx.z;
    int cnt = g_cnt[e];
    int base = blockIdx.x * BM;
    if (base >= cnt) return;
    int nb = blockIdx.y * BN;

    extern __shared__ char smem[];
    const uint32_t su = smem_u32(smem);
    int* stok = (int*)(smem + SMETA);
    int* srow = (int*)(smem + SMETA + 512);

    int t = threadIdx.x;
    int wid = t >> 5, l = t & 31;
    int wm = wid >> 2, wn = wid & 3;

    if (t < BM) {
        int idx = base + t;
        stok[t] = (idx < cnt) ? g_tok[e * N_TOK + idx] : 0;
        srow[t] = (idx < cnt) ? g_row[e * N_TOK + idx] : -1;
    }
    __syncthreads();

    float acc[4][4][4];
#pragma unroll
    for (int mi = 0; mi < 4; mi++)
#pragma unroll
        for (int ni = 0; ni < 4; ni++)
#pragma unroll
            for (int c = 0; c < 4; c++) acc[mi][ni][c] = 0.f;

    size_t bbase = (size_t)e * H + nb;
    const int NK = D / KC;   // 8

    stage_chunk(su, t, g_xh, g_xl, stok, D, g_w1h, g_w1l, bbase, D, 0);
    CP_COMMIT();
#pragma unroll 1
    for (int k = 0; k < NK; k++) {
        if (k + 1 < NK) {
            stage_chunk(su + ((k + 1) & 1) * STAGE_BYTES, t,
                        g_xh, g_xl, stok, D, g_w1h, g_w1l, bbase, D, (k + 1) * KC);
            CP_COMMIT();
            CP_WAIT(1);
        } else {
            CP_WAIT(0);
        }
        __syncthreads();
        tile_mma(su + (k & 1) * STAGE_BYTES, wm, wn, l, acc);
        __syncthreads();
    }

    // epilogue: bias + gelu + hi/lo split -> g_hh/g_hl
    const float* b1e = b1 + e * H;
#pragma unroll
    for (int mi = 0; mi < 4; mi++) {
        int m0 = wm * 64 + mi * 16 + (l >> 2);
        int r0 = srow[m0], r1 = srow[m0 + 8];
#pragma unroll
        for (int ni = 0; ni < 4; ni++) {
            int col = nb + wn * 32 + ni * 8 + (l & 3) * 2;
            float ba = b1e[col], bb = b1e[col + 1];
#pragma unroll
            for (int half = 0; half < 2; half++) {
                int r = half ? r1 : r0;
                if (r < 0) continue;
                float g0 = gelu_exact(acc[mi][ni][half * 2 + 0] + ba);
                float g1 = gelu_exact(acc[mi][ni][half * 2 + 1] + bb);
                __nv_bfloat16 h0 = __float2bfloat16_rn(g0);
                __nv_bfloat16 h1 = __float2bfloat16_rn(g1);
                __nv_bfloat16 l0 = __float2bfloat16_rn(g0 - __bfloat162float(h0));
                __nv_bfloat16 l1 = __float2bfloat16_rn(g1 - __bfloat162float(h1));
                __nv_bfloat162 hp, lp;
                hp.x = h0; hp.y = h1; lp.x = l0; lp.y = l1;
                *(__nv_bfloat162*)(g_hh + (size_t)r * H + col) = hp;
                *(__nv_bfloat162*)(g_hl + (size_t)r * H + col) = lp;
            }
        }
    }
}

// ------------------------- GEMM2: out += w * (h W2 + b2) ---------------
__global__ void __launch_bounds__(THREADS, 2) gemm2_kernel(const float* __restrict__ b2,
                                                           float* __restrict__ out) {
    int e = blockIdx.z;
    int cnt = g_cnt[e];
    int base = blockIdx.x * BM;
    if (base >= cnt) return;
    int nb = blockIdx.y * BN;

    extern __shared__ char smem[];
    const uint32_t su = smem_u32(smem);
    int*   stok = (int*)(smem + SMETA);
    int*   srow = (int*)(smem + SMETA + 512);
    float* swgt = (float*)(smem + SMETA + 1024);

    int t = threadIdx.x;
    int wid = t >> 5, l = t & 31;
    int wm = wid >> 2, wn = wid & 3;

    if (t < BM) {
        int idx = base + t;
        stok[t] = (idx < cnt) ? g_tok[e * N_TOK + idx] : 0;
        srow[t] = (idx < cnt) ? g_row[e * N_TOK + idx] : 0;
        swgt[t] = (idx < cnt) ? g_wgt[e * N_TOK + idx] : 0.f;
    }
    __syncthreads();

    float acc[4][4][4];
#pragma unroll
    for (int mi = 0; mi < 4; mi++)
#pragma unroll
        for (int ni = 0; ni < 4; ni++)
#pragma unroll
            for (int c = 0; c < 4; c++) acc[mi][ni][c] = 0.f;

    size_t bbase = (size_t)e * D + nb;
    const int NK = H / KC;   // 32

    stage_chunk(su, t, g_hh, g_hl, srow, H, g_w2h, g_w2l, bbase, H, 0);
    CP_COMMIT();
#pragma unroll 1
    for (int k = 0; k < NK; k++) {
        if (k + 1 < NK) {
            stage_chunk(su + ((k + 1) & 1) * STAGE_BYTES, t,
                        g_hh, g_hl, srow, H, g_w2h, g_w2l, bbase, H, (k + 1) * KC);
            CP_COMMIT();
            CP_WAIT(1);
        } else {
            CP_WAIT(0);
        }
        __syncthreads();
        tile_mma(su + (k & 1) * STAGE_BYTES, wm, wn, l, acc);
        __syncthreads();
    }

    // epilogue: out[token] += w * (acc + b2)
    const float* b2e = b2 + e * D;
#pragma unroll
    for (int mi = 0; mi < 4; mi++) {
        int m0 = wm * 64 + mi * 16 + (l >> 2);
#pragma unroll
        for (int half = 0; half < 2; half++) {
            int m = m0 + half * 8;
            float w = swgt[m];
            if (w == 0.f) continue;
            int tok = stok[m];
            float* op = out + (size_t)tok * D;
#pragma unroll
            for (int ni = 0; ni < 4; ni++) {
                int col = nb + wn * 32 + ni * 8 + (l & 3) * 2;
                atomicAdd(op + col,     w * (acc[mi][ni][half * 2 + 0] + b2e[col]));
                atomicAdd(op + col + 1, w * (acc[mi][ni][half * 2 + 1] + b2e[col + 1]));
            }
        }
    }
}

// --------------------------------- launch --------------------------------
extern "C" void kernel_launch(void* const* d_in, const int* in_sizes, int n_in,
                              void* d_out, int out_size) {
    const float* x    = (const float*)d_in[0];
    const float* grad = (const float*)d_in[1];
    const float* Wr   = (const float*)d_in[2];
    const float* br   = (const float*)d_in[3];
    const float* W1   = (const float*)d_in[4];
    const float* b1   = (const float*)d_in[5];
    const float* W2   = (const float*)d_in[6];
    const float* b2   = (const float*)d_in[7];

    float* out   = (float*)d_out;                       // [N, D]
    float* probs = (float*)d_out + (size_t)N_TOK * D;   // [N, E]

    static int attr_set = 0;
    if (!attr_set) {
        cudaFuncSetAttribute(gemm1_kernel,
                             cudaFuncAttributeMaxDynamicSharedMemorySize, SMEM_BYTES);
        cudaFuncSetAttribute(gemm2_kernel,
                             cudaFuncAttributeMaxDynamicSharedMemorySize, SMEM_BYTES);
        attr_set = 1;
    }

    prep_x_kernel<<<(N_TOK * D / 4 + 255) / 256, 256>>>(x, out);
    {
        dim3 g(H / 32, D / 32, E), b(32, 8);   // W1: n over H, k over D
        w1t_kernel<<<g, b>>>(W1);
    }
    {
        dim3 g(D / 32, H / 32, E), b(32, 8);   // W2: n over D, k over H
        w2t_kernel<<<g, b>>>(W2);
    }
    router_kernel<<<N_TOK / RT_TOK, 256>>>(x, grad, Wr, br, probs);
    {
        dim3 grid(N_TOK / BM, H / BN, E);   // (256, 8, 8)
        gemm1_kernel<<<grid, THREADS, SMEM_BYTES>>>(b1);
    }
    {
        dim3 grid(N_TOK / BM, D / BN, E);   // (256, 2, 8)
        gemm2_kernel<<<grid, THREADS, SMEM_BYTES>>>(b2, out);
    }
}